// round 16
// baseline (speedup 1.0000x reference)
#include <cuda_runtime.h>
#include <cuda_fp16.h>
#include <cstdint>

// Problem constants: B_=2048, N=49, C=384, H=12, d=32, nW=64
#define BWIN   2048
#define NTOK   49
#define CDIM   384
#define HNUM   12
#define DHEAD  32
#define NWIN   64
#define MROWS  (BWIN * NTOK)     // 100352
#define QKVC   (3 * CDIM)        // 1152
#define KDIM   384

// GEMM tiling (R12/R15 shape: 128x128 tile, 1 M-tile/CTA, 2 CTAs/SM)
#define GBM   128
#define GBN   128
#define GKC   64
#define NCH   6
#define NSTG  3
#define ROWB  144
#define A_ST  (GBM * ROWB)
#define B_ST  (GBN * ROWB)
#define STG_B (A_ST + B_ST)
#define SMEM_GEMM (NSTG * STG_B) // 110592 -> 2 CTAs/SM
#define MTILES (MROWS / GBM)     // 784

#define PX_BLKS  37632
#define WQ_BLKS  1728
#define WP_BLKS  576
#define PAD_BLKS 12288           // 786432 vt rows x 4 uint2 pad zeros

#define BSTR 50
#define SCALE 0.17677669529663687f

// -------------------- device scratch --------------------------------------
__device__ __align__(16) __half g_xh  [(size_t)MROWS * KDIM];
__device__ __align__(16) __half g_attf[(size_t)MROWS * CDIM];
__device__ __align__(16) __half g_qkh [(size_t)MROWS * 768];      // q|k, frag-permuted
__device__ __align__(16) __half g_vt  [(size_t)BWIN * CDIM * 64]; // vT, frag-permuted
__device__ __align__(16) __half g_wq  [(size_t)QKVC * KDIM];
__device__ __align__(16) __half g_wp  [(size_t)CDIM * KDIM];

// -------------------- PTX helpers -----------------------------------------
__device__ __forceinline__ uint32_t smem_u32(const void* p) {
    uint32_t a;
    asm("{ .reg .u64 t; cvta.to.shared.u64 t, %1; cvt.u32.u64 %0, t; }"
        : "=r"(a) : "l"(p));
    return a;
}
__device__ __forceinline__ void cp16(uint32_t s, const void* g) {
    asm volatile("cp.async.cg.shared.global [%0], [%1], 16;" :: "r"(s), "l"(g));
}
__device__ __forceinline__ void cp_commit() {
    asm volatile("cp.async.commit_group;" ::: "memory");
}
__device__ __forceinline__ void ldsm4(uint32_t* r, uint32_t addr) {
    asm volatile("ldmatrix.sync.aligned.m8n8.x4.shared.b16 {%0,%1,%2,%3}, [%4];"
        : "=r"(r[0]), "=r"(r[1]), "=r"(r[2]), "=r"(r[3]) : "r"(addr));
}
__device__ __forceinline__ void mma16816(float* d, const uint32_t* a, const uint32_t* b) {
    asm volatile(
        "mma.sync.aligned.m16n8k16.row.col.f32.f16.f16.f32 "
        "{%0,%1,%2,%3}, {%4,%5,%6,%7}, {%8,%9}, {%0,%1,%2,%3};"
        : "+f"(d[0]), "+f"(d[1]), "+f"(d[2]), "+f"(d[3])
        : "r"(a[0]), "r"(a[1]), "r"(a[2]), "r"(a[3]), "r"(b[0]), "r"(b[1]));
}
__device__ __forceinline__ uint32_t pack2(__half lo, __half hi) {
    return (uint32_t)__half_as_ushort(lo) | ((uint32_t)__half_as_ushort(hi) << 16);
}

// -------------------- fused prep -------------------------------------------
__global__ __launch_bounds__(256)
void prep_all_kernel(const float* __restrict__ x,
                     const float* __restrict__ qkv_w,
                     const float* __restrict__ proj_w)
{
    const int bid = blockIdx.x;
    const int tid = threadIdx.x;

    if (bid < PX_BLKS) {
        size_t id = (size_t)bid * 256 + tid;
        size_t row = id / 96;
        int c4 = (int)(id % 96) * 4;
        float4 v = *reinterpret_cast<const float4*>(&x[row * KDIM + c4]);
        __half h[4];
        h[0] = __float2half_rn(v.x); h[1] = __float2half_rn(v.y);
        h[2] = __float2half_rn(v.z); h[3] = __float2half_rn(v.w);
        *reinterpret_cast<uint2*>(&g_xh[row * KDIM + c4]) = *reinterpret_cast<uint2*>(h);
    } else if (bid < PX_BLKS + WQ_BLKS) {
        int id = (bid - PX_BLKS) * 256 + tid;
        if (id < KDIM * QKVC) {
            int k = id / QKVC, n = id % QKVC;
            g_wq[(size_t)n * KDIM + k] = __float2half_rn(qkv_w[(size_t)k * QKVC + n]);
        }
    } else if (bid < PX_BLKS + WQ_BLKS + WP_BLKS) {
        int id = (bid - PX_BLKS - WQ_BLKS) * 256 + tid;
        if (id < KDIM * CDIM) {
            int k = id / CDIM, n = id % CDIM;
            g_wp[(size_t)n * KDIM + k] = __float2half_rn(proj_w[(size_t)k * CDIM + n]);
        }
    } else {
        // zero vt pad: in permuted key layout, invalid keys (>=49, plus key 48
        // which the GEMM rewrites) occupy the last 8B of each 32B block.
        size_t s = (size_t)(bid - PX_BLKS - WQ_BLKS - WP_BLKS) * 256 + tid;
        size_t row = s >> 2;
        int q = (int)(s & 3);
        if (row < (size_t)BWIN * CDIM) {
            *reinterpret_cast<uint2*>(
                reinterpret_cast<char*>(g_vt) + row * 128 + q * 32 + 24) =
                make_uint2(0, 0);
        }
    }
}

// -------------------- GEMM (R15 shape; frag-permuted outputs) ---------------
// mode 0: fp32 out to Cv (ldc stride)                         (proj)
// mode 3: qkv fused — col<384: q*SCALE; 384..767: k — both permuted within
//         each 32-elem head group; col>=768: v scatter to permuted vt rows.
__global__ __launch_bounds__(256, 2)
void gemm_fp16_kernel(const __half* __restrict__ Ab, int lda,
                      const __half* __restrict__ Bt,
                      const float* __restrict__ bias,
                      void* __restrict__ Cv, int ldc, int mode)
{
    extern __shared__ char smem[];
    const uint32_t s0 = smem_u32(smem);

    const int tid  = threadIdx.x;
    const int wid  = tid >> 5;
    const int lane = tid & 31;
    const int wm   = wid >> 1;
    const int wn   = wid & 1;
    const int bn   = blockIdx.x * GBN;
    const int bm   = blockIdx.y * GBM;

    const int lrow = tid >> 3;
    const int seg  = tid & 7;

    float acc[2][8][4];
#pragma unroll
    for (int i = 0; i < 2; ++i)
#pragma unroll
        for (int j = 0; j < 8; ++j)
#pragma unroll
            for (int q = 0; q < 4; ++q) acc[i][j][q] = 0.f;

    const int a_r  = (lane & 7) + ((lane >> 3) & 1) * 8;
    const int a_cb = (lane >> 4) * 16;
    const int b_r  = (lane & 7) + ((lane >> 4) & 1) * 8;
    const int b_cb = ((lane >> 3) & 1) * 16;

    auto issue = [&](int kc, int stg) {
        const int kp = kc * GKC;
        const uint32_t sa  = s0 + stg * STG_B;
        const uint32_t sbb = sa + A_ST;
#pragma unroll
        for (int i = 0; i < 4; ++i) {
            int r = lrow + i * 32;
            cp16(sa + r * ROWB + seg * 16,
                 Ab + (size_t)(bm + r) * lda + kp + seg * 8);
        }
#pragma unroll
        for (int i = 0; i < 4; ++i) {
            int r = lrow + i * 32;
            cp16(sbb + r * ROWB + seg * 16,
                 Bt + (size_t)(bn + r) * KDIM + kp + seg * 8);
        }
        cp_commit();
    };

    issue(0, 0);
    issue(1, 1);

    for (int kc = 0; kc < NCH; ++kc) {
        if (kc < NCH - 1)
            asm volatile("cp.async.wait_group 1;" ::: "memory");
        else
            asm volatile("cp.async.wait_group 0;" ::: "memory");
        __syncthreads();

        if (kc + 2 < NCH) issue(kc + 2, (kc + 2) % NSTG);

        const uint32_t sa = s0 + (kc % NSTG) * STG_B;
        const uint32_t abase = sa + (wm * 32 + a_r) * ROWB + a_cb;
        const uint32_t bbase = sa + A_ST + (wn * 64 + b_r) * ROWB + b_cb;

#pragma unroll
        for (int ks = 0; ks < 4; ++ks) {
            const int kb = ks * 32;
            uint32_t af[2][4];
#pragma unroll
            for (int fm = 0; fm < 2; ++fm)
                ldsm4(af[fm], abase + fm * 16 * ROWB + kb);
            uint32_t bfr[8][2];
#pragma unroll
            for (int j = 0; j < 4; ++j) {
                uint32_t r[4];
                ldsm4(r, bbase + j * 16 * ROWB + kb);
                bfr[2 * j][0] = r[0]; bfr[2 * j][1] = r[1];
                bfr[2 * j + 1][0] = r[2]; bfr[2 * j + 1][1] = r[3];
            }
#pragma unroll
            for (int fm = 0; fm < 2; ++fm)
#pragma unroll
                for (int fn = 0; fn < 8; ++fn)
                    mma16816(acc[fm][fn], af[fm], bfr[fn]);
        }
    }

#pragma unroll
    for (int fm = 0; fm < 2; ++fm) {
        const int row0 = bm + wm * 32 + fm * 16 + (lane >> 2);
        const int b0 = row0 / NTOK,        n0 = row0 - b0 * NTOK;
        const int b1 = (row0 + 8) / NTOK,  n1 = (row0 + 8) - b1 * NTOK;
#pragma unroll
        for (int fn = 0; fn < 8; ++fn) {
            const int col = bn + wn * 64 + fn * 8 + (lane & 3) * 2;
            const float b0f = __ldg(&bias[col]);
            const float b1f = __ldg(&bias[col + 1]);
            float o0 = acc[fm][fn][0] + b0f, o1 = acc[fm][fn][1] + b1f;
            float o2 = acc[fm][fn][2] + b0f, o3 = acc[fm][fn][3] + b1f;
            if (mode == 0) {
                float* C = (float*)Cv;
                *reinterpret_cast<float2*>(&C[(size_t)row0 * ldc + col]) =
                    make_float2(o0, o1);
                *reinterpret_cast<float2*>(&C[(size_t)(row0 + 8) * ldc + col]) =
                    make_float2(o2, o3);
            } else if (col < 768) {
                if (col < 384) {        // q: fold softmax scale
                    o0 *= SCALE; o1 *= SCALE; o2 *= SCALE; o3 *= SCALE;
                }
                // permute within 32-elem head group: d -> g*8 + slot*2 (+sub)
                const int d   = col & 31;                 // even
                const int pos = ((d & 7) >> 1) * 8 + ((d >> 3) << 1);
                const int cb  = (col & ~31) + pos;
                *reinterpret_cast<uint32_t*>(&g_qkh[(size_t)row0 * 768 + cb]) =
                    pack2(__float2half_rn(o0), __float2half_rn(o1));
                *reinterpret_cast<uint32_t*>(&g_qkh[(size_t)(row0 + 8) * 768 + cb]) =
                    pack2(__float2half_rn(o2), __float2half_rn(o3));
            } else {
                const int cv = col - 768;
                // permute key within 64-key row: k -> g*16 + slot*2 + sub
                const int p0 = ((n0 & 7) >> 1) * 16 + ((n0 >> 3) << 1) + (n0 & 1);
                const int p1 = ((n1 & 7) >> 1) * 16 + ((n1 >> 3) << 1) + (n1 & 1);
                const size_t i0 = ((size_t)b0 * CDIM + cv) * 64 + p0;
                const size_t i1 = ((size_t)b1 * CDIM + cv) * 64 + p1;
                g_vt[i0]      = __float2half_rn(o0);
                g_vt[i0 + 64] = __float2half_rn(o1);
                g_vt[i1]      = __float2half_rn(o2);
                g_vt[i1 + 64] = __float2half_rn(o3);
            }
        }
    }
}

// -------------------- MMA attention: uint4 frag loads, deferred K -----------
__global__ __launch_bounds__(256)
void attn_mma_kernel(const float* __restrict__ relb,
                     const float* __restrict__ mask)
{
    __shared__ float bias_s[NTOK * BSTR];

    const int w = blockIdx.x, h = blockIdx.y;
    const int tid = threadIdx.x, warp = tid >> 5, lane = tid & 31;
    const int kq = lane >> 2;
    const int kc = (lane & 3) * 2;
    const int g  = lane & 3;                 // perm block index

    {
        const float* rb = relb + (size_t)h * NTOK * NTOK;
        const float* mk = mask + (size_t)w * NTOK * NTOK;
        for (int i = tid; i < NTOK * NTOK; i += 256)
            bias_s[(i / NTOK) * BSTR + (i % NTOK)] = rb[i] + mk[i];
    }
    __syncthreads();

    for (int win = 0; win < 4; ++win) {
        const int j = warp * 4 + win;        // 0..31
        const int b = j * 64 + w;
        const __half* qsec = g_qkh + (size_t)b * NTOK * 768 + h * DHEAD;
        const __half* ksec = qsec + 384;
        const __half* vrow = g_vt + ((size_t)b * CDIM + h * DHEAD) * 64;

        // V frags: one 32B (2 x uint4) read per d-row — resident across mt
        uint32_t vhf[4][4][2];
#pragma unroll
        for (int nt = 0; nt < 4; ++nt) {
            const __half* p = vrow + (size_t)(nt * 8 + kq) * 64 + g * 16;
            const uint4 u0 = *reinterpret_cast<const uint4*>(p);
            const uint4 u1 = *reinterpret_cast<const uint4*>(p + 8);
            vhf[nt][0][0] = u0.x; vhf[nt][0][1] = u0.y;
            vhf[nt][1][0] = u0.z; vhf[nt][1][1] = u0.w;
            vhf[nt][2][0] = u1.x; vhf[nt][2][1] = u1.y;
            vhf[nt][3][0] = u1.z; vhf[nt][3][1] = u1.w;
        }

        for (int mt = 0; mt < 4; ++mt) {
            const int row = mt * 16 + kq;
            const bool r0ok = (row < NTOK), r1ok = (row + 8 < NTOK);

            // Q frags: one uint4 per row
            uint32_t qf[2][4];
            {
                uint4 u0 = make_uint4(0, 0, 0, 0), u1 = make_uint4(0, 0, 0, 0);
                if (r0ok) u0 = *reinterpret_cast<const uint4*>(
                                   qsec + (size_t)row * 768 + g * 8);
                if (r1ok) u1 = *reinterpret_cast<const uint4*>(
                                   qsec + (size_t)(row + 8) * 768 + g * 8);
                qf[0][0] = u0.x; qf[0][2] = u0.y; qf[1][0] = u0.z; qf[1][2] = u0.w;
                qf[0][1] = u1.x; qf[0][3] = u1.y; qf[1][1] = u1.z; qf[1][3] = u1.w;
            }

            // K frags: deferred (reloaded per mt from L1), one uint4 per key
            uint32_t kf[7][2][2];
#pragma unroll
            for (int nt = 0; nt < 7; ++nt) {
                const int key = nt * 8 + kq;
                uint4 u = make_uint4(0, 0, 0, 0);
                if (key < NTOK)
                    u = *reinterpret_cast<const uint4*>(
                            ksec + (size_t)key * 768 + g * 8);
                kf[nt][0][0] = u.x; kf[nt][0][1] = u.y;
                kf[nt][1][0] = u.z; kf[nt][1][1] = u.w;
            }

            float sf[7][4];
#pragma unroll
            for (int nt = 0; nt < 7; ++nt) {
                sf[nt][0] = sf[nt][1] = sf[nt][2] = sf[nt][3] = 0.f;
                mma16816(sf[nt], qf[0], kf[nt][0]);
                mma16816(sf[nt], qf[1], kf[nt][1]);
            }

            const int n0 = (row < 48) ? row : 48;
            const int n1 = (row + 8 < 48) ? (row + 8) : 48;
            float sum0 = 0.f, sum1 = 0.f;
#pragma unroll
            for (int nt = 0; nt < 7; ++nt) {
                const int key = nt * 8 + kc;
                const float2 bq0 = *reinterpret_cast<const float2*>(&bias_s[n0 * BSTR + key]);
                const float2 bq1 = *reinterpret_cast<const float2*>(&bias_s[n1 * BSTR + key]);
                float e0 = __expf(sf[nt][0] + bq0.x);
                float e1 = __expf(sf[nt][1] + bq0.y);
                float e2 = __expf(sf[nt][2] + bq1.x);
                float e3 = __expf(sf[nt][3] + bq1.y);
                if (nt == 6) {
                    if (kc != 0) { e0 = 0.f; e2 = 0.f; }
                    e1 = 0.f; e3 = 0.f;
                }
                sf[nt][0] = e0; sf[nt][1] = e1; sf[nt][2] = e2; sf[nt][3] = e3;
                sum0 += e0 + e1; sum1 += e2 + e3;
            }
            sum0 += __shfl_xor_sync(0xffffffffu, sum0, 1);
            sum0 += __shfl_xor_sync(0xffffffffu, sum0, 2);
            sum1 += __shfl_xor_sync(0xffffffffu, sum1, 1);
            sum1 += __shfl_xor_sync(0xffffffffu, sum1, 2);
            const float inv0 = 1.f / sum0, inv1 = 1.f / sum1;

            float of[4][4];
#pragma unroll
            for (int nt = 0; nt < 4; ++nt)
                of[nt][0] = of[nt][1] = of[nt][2] = of[nt][3] = 0.f;

#pragma unroll
            for (int kt = 0; kt < 4; ++kt) {
                float e[8];
                e[0] = sf[2 * kt][0]; e[1] = sf[2 * kt][1];
                e[2] = sf[2 * kt][2]; e[3] = sf[2 * kt][3];
                if (2 * kt + 1 < 7) {
                    e[4] = sf[2 * kt + 1][0]; e[5] = sf[2 * kt + 1][1];
                    e[6] = sf[2 * kt + 1][2]; e[7] = sf[2 * kt + 1][3];
                } else {
                    e[4] = e[5] = e[6] = e[7] = 0.f;
                }
                __half hb[8], lb[8];
#pragma unroll
                for (int i = 0; i < 8; ++i) {
                    hb[i] = __float2half_rn(e[i]);
                    lb[i] = __float2half_rn(e[i] - __half2float(hb[i]));
                }
                uint32_t ph[4], pl[4];
                ph[0] = pack2(hb[0], hb[1]); ph[1] = pack2(hb[2], hb[3]);
                ph[2] = pack2(hb[4], hb[5]); ph[3] = pack2(hb[6], hb[7]);
                pl[0] = pack2(lb[0], lb[1]); pl[1] = pack2(lb[2], lb[3]);
                pl[2] = pack2(lb[4], lb[5]); pl[3] = pack2(lb[6], lb[7]);
#pragma unroll
                for (int nt = 0; nt < 4; ++nt) {
                    mma16816(of[nt], ph, vhf[nt][kt]);
                    mma16816(of[nt], pl, vhf[nt][kt]);
                }
            }

            const size_t r0 = ((size_t)b * NTOK + row) * CDIM + h * DHEAD;
            const size_t r1 = ((size_t)b * NTOK + row + 8) * CDIM + h * DHEAD;
#pragma unroll
            for (int nt = 0; nt < 4; ++nt) {
                const int d = nt * 8 + kc;
                if (r0ok) {
                    *reinterpret_cast<uint32_t*>(&g_attf[r0 + d]) =
                        pack2(__float2half_rn(of[nt][0] * inv0),
                              __float2half_rn(of[nt][1] * inv0));
                }
                if (r1ok) {
                    *reinterpret_cast<uint32_t*>(&g_attf[r1 + d]) =
                        pack2(__float2half_rn(of[nt][2] * inv1),
                              __float2half_rn(of[nt][3] * inv1));
                }
            }
        }
    }
}

// ---------------------------------------------------------------------------
extern "C" void kernel_launch(void* const* d_in, const int* in_sizes, int n_in,
                              void* d_out, int out_size)
{
    const float* x      = (const float*)d_in[0];
    const float* mask   = (const float*)d_in[1];
    const float* qkv_w  = (const float*)d_in[2];
    const float* qkv_b  = (const float*)d_in[3];
    const float* proj_w = (const float*)d_in[4];
    const float* proj_b = (const float*)d_in[5];
    const float* relb   = (const float*)d_in[6];
    float* out = (float*)d_out;

    void *p_xh, *p_attf, *p_wq, *p_wp;
    cudaGetSymbolAddress(&p_xh,   g_xh);
    cudaGetSymbolAddress(&p_attf, g_attf);
    cudaGetSymbolAddress(&p_wq,   g_wq);
    cudaGetSymbolAddress(&p_wp,   g_wp);

    cudaFuncSetAttribute(gemm_fp16_kernel,
                         cudaFuncAttributeMaxDynamicSharedMemorySize, SMEM_GEMM);

    // 0) fused preps
    prep_all_kernel<<<PX_BLKS + WQ_BLKS + WP_BLKS + PAD_BLKS, 256>>>(x, qkv_w, proj_w);

    // 1) fused QKV GEMM (R15 shape, permuted q/k/v outputs)
    {
        dim3 grid(QKVC / GBN, MTILES);    // 9 x 784
        gemm_fp16_kernel<<<grid, 256, SMEM_GEMM>>>(
            (const __half*)p_xh, KDIM, (const __half*)p_wq,
            qkv_b, nullptr, 0, 3);
    }
    // 2) MMA attention (uint4 frag loads, deferred K)
    {
        dim3 grid(NWIN, HNUM);
        attn_mma_kernel<<<grid, 256>>>(relb, mask);
    }
    // 3) projection GEMM
    {
        dim3 grid(CDIM / GBN, MTILES);    // 3 x 784
        gemm_fp16_kernel<<<grid, 256, SMEM_GEMM>>>(
            (const __half*)p_attf, CDIM, (const __half*)p_wp,
            proj_b, out, CDIM, 0);
    }
}

// round 17
// speedup vs baseline: 1.0106x; 1.0106x over previous
#include <cuda_runtime.h>
#include <cuda_fp16.h>
#include <cstdint>

// Problem constants: B_=2048, N=49, C=384, H=12, d=32, nW=64
#define BWIN   2048
#define NTOK   49
#define CDIM   384
#define HNUM   12
#define DHEAD  32
#define NWIN   64
#define MROWS  (BWIN * NTOK)     // 100352
#define QKVC   (3 * CDIM)        // 1152
#define KDIM   384

// GEMM tiling (R12/R15 shape: 128x128 tile, 1 M-tile/CTA, 2 CTAs/SM)
#define GBM   128
#define GBN   128
#define GKC   64
#define NCH   6
#define NSTG  3
#define ROWB  144
#define A_ST  (GBM * ROWB)
#define B_ST  (GBN * ROWB)
#define STG_B (A_ST + B_ST)
#define SMEM_GEMM (NSTG * STG_B) // 110592 -> 2 CTAs/SM
#define MTILES (MROWS / GBM)     // 784

#define PX_BLKS  37632
#define WQ_BLKS  1728
#define WP_BLKS  576
#define PAD_BLKS 12288           // 786432 vt rows x 4 uint2 pad zeros

#define BSTR 50
#define SCALE 0.17677669529663687f

// -------------------- device scratch --------------------------------------
__device__ __align__(16) __half g_xh  [(size_t)MROWS * KDIM];
__device__ __align__(16) __half g_attf[(size_t)MROWS * CDIM];
__device__ __align__(16) __half g_qkh [(size_t)MROWS * 768];      // q|k, frag-permuted
__device__ __align__(16) __half g_vt  [(size_t)BWIN * CDIM * 64]; // vT, frag-permuted
__device__ __align__(16) __half g_wq  [(size_t)QKVC * KDIM];
__device__ __align__(16) __half g_wp  [(size_t)CDIM * KDIM];

// -------------------- PTX helpers -----------------------------------------
__device__ __forceinline__ uint32_t smem_u32(const void* p) {
    uint32_t a;
    asm("{ .reg .u64 t; cvta.to.shared.u64 t, %1; cvt.u32.u64 %0, t; }"
        : "=r"(a) : "l"(p));
    return a;
}
__device__ __forceinline__ void cp16(uint32_t s, const void* g) {
    asm volatile("cp.async.cg.shared.global [%0], [%1], 16;" :: "r"(s), "l"(g));
}
__device__ __forceinline__ void cp_commit() {
    asm volatile("cp.async.commit_group;" ::: "memory");
}
__device__ __forceinline__ void ldsm4(uint32_t* r, uint32_t addr) {
    asm volatile("ldmatrix.sync.aligned.m8n8.x4.shared.b16 {%0,%1,%2,%3}, [%4];"
        : "=r"(r[0]), "=r"(r[1]), "=r"(r[2]), "=r"(r[3]) : "r"(addr));
}
__device__ __forceinline__ void mma16816(float* d, const uint32_t* a, const uint32_t* b) {
    asm volatile(
        "mma.sync.aligned.m16n8k16.row.col.f32.f16.f16.f32 "
        "{%0,%1,%2,%3}, {%4,%5,%6,%7}, {%8,%9}, {%0,%1,%2,%3};"
        : "+f"(d[0]), "+f"(d[1]), "+f"(d[2]), "+f"(d[3])
        : "r"(a[0]), "r"(a[1]), "r"(a[2]), "r"(a[3]), "r"(b[0]), "r"(b[1]));
}
__device__ __forceinline__ uint32_t pack2(__half lo, __half hi) {
    return (uint32_t)__half_as_ushort(lo) | ((uint32_t)__half_as_ushort(hi) << 16);
}

// -------------------- fused prep -------------------------------------------
__global__ __launch_bounds__(256)
void prep_all_kernel(const float* __restrict__ x,
                     const float* __restrict__ qkv_w,
                     const float* __restrict__ proj_w)
{
    const int bid = blockIdx.x;
    const int tid = threadIdx.x;

    if (bid < PX_BLKS) {
        size_t id = (size_t)bid * 256 + tid;
        size_t row = id / 96;
        int c4 = (int)(id % 96) * 4;
        float4 v = *reinterpret_cast<const float4*>(&x[row * KDIM + c4]);
        __half h[4];
        h[0] = __float2half_rn(v.x); h[1] = __float2half_rn(v.y);
        h[2] = __float2half_rn(v.z); h[3] = __float2half_rn(v.w);
        *reinterpret_cast<uint2*>(&g_xh[row * KDIM + c4]) = *reinterpret_cast<uint2*>(h);
    } else if (bid < PX_BLKS + WQ_BLKS) {
        int id = (bid - PX_BLKS) * 256 + tid;
        if (id < KDIM * QKVC) {
            int k = id / QKVC, n = id % QKVC;
            g_wq[(size_t)n * KDIM + k] = __float2half_rn(qkv_w[(size_t)k * QKVC + n]);
        }
    } else if (bid < PX_BLKS + WQ_BLKS + WP_BLKS) {
        int id = (bid - PX_BLKS - WQ_BLKS) * 256 + tid;
        if (id < KDIM * CDIM) {
            int k = id / CDIM, n = id % CDIM;
            g_wp[(size_t)n * KDIM + k] = __float2half_rn(proj_w[(size_t)k * CDIM + n]);
        }
    } else {
        // zero vt pad: in permuted key layout, invalid keys occupy the last
        // 8B of each 32B block (key 48 is rewritten by the GEMM afterwards).
        size_t s = (size_t)(bid - PX_BLKS - WQ_BLKS - WP_BLKS) * 256 + tid;
        size_t row = s >> 2;
        int q = (int)(s & 3);
        if (row < (size_t)BWIN * CDIM) {
            *reinterpret_cast<uint2*>(
                reinterpret_cast<char*>(g_vt) + row * 128 + q * 32 + 24) =
                make_uint2(0, 0);
        }
    }
}

// -------------------- GEMM (R15 shape; frag-permuted outputs) ---------------
// mode 0: fp32 out to Cv (ldc stride)                         (proj)
// mode 3: qkv fused — col<384: q*SCALE; 384..767: k — both permuted within
//         each 32-elem head group; col>=768: v scatter to permuted vt rows.
__global__ __launch_bounds__(256, 2)
void gemm_fp16_kernel(const __half* __restrict__ Ab, int lda,
                      const __half* __restrict__ Bt,
                      const float* __restrict__ bias,
                      void* __restrict__ Cv, int ldc, int mode)
{
    extern __shared__ char smem[];
    const uint32_t s0 = smem_u32(smem);

    const int tid  = threadIdx.x;
    const int wid  = tid >> 5;
    const int lane = tid & 31;
    const int wm   = wid >> 1;
    const int wn   = wid & 1;
    const int bn   = blockIdx.x * GBN;
    const int bm   = blockIdx.y * GBM;

    const int lrow = tid >> 3;
    const int seg  = tid & 7;

    float acc[2][8][4];
#pragma unroll
    for (int i = 0; i < 2; ++i)
#pragma unroll
        for (int j = 0; j < 8; ++j)
#pragma unroll
            for (int q = 0; q < 4; ++q) acc[i][j][q] = 0.f;

    const int a_r  = (lane & 7) + ((lane >> 3) & 1) * 8;
    const int a_cb = (lane >> 4) * 16;
    const int b_r  = (lane & 7) + ((lane >> 4) & 1) * 8;
    const int b_cb = ((lane >> 3) & 1) * 16;

    auto issue = [&](int kc, int stg) {
        const int kp = kc * GKC;
        const uint32_t sa  = s0 + stg * STG_B;
        const uint32_t sbb = sa + A_ST;
#pragma unroll
        for (int i = 0; i < 4; ++i) {
            int r = lrow + i * 32;
            cp16(sa + r * ROWB + seg * 16,
                 Ab + (size_t)(bm + r) * lda + kp + seg * 8);
        }
#pragma unroll
        for (int i = 0; i < 4; ++i) {
            int r = lrow + i * 32;
            cp16(sbb + r * ROWB + seg * 16,
                 Bt + (size_t)(bn + r) * KDIM + kp + seg * 8);
        }
        cp_commit();
    };

    issue(0, 0);
    issue(1, 1);

    for (int kc = 0; kc < NCH; ++kc) {
        if (kc < NCH - 1)
            asm volatile("cp.async.wait_group 1;" ::: "memory");
        else
            asm volatile("cp.async.wait_group 0;" ::: "memory");
        __syncthreads();

        if (kc + 2 < NCH) issue(kc + 2, (kc + 2) % NSTG);

        const uint32_t sa = s0 + (kc % NSTG) * STG_B;
        const uint32_t abase = sa + (wm * 32 + a_r) * ROWB + a_cb;
        const uint32_t bbase = sa + A_ST + (wn * 64 + b_r) * ROWB + b_cb;

#pragma unroll
        for (int ks = 0; ks < 4; ++ks) {
            const int kb = ks * 32;
            uint32_t af[2][4];
#pragma unroll
            for (int fm = 0; fm < 2; ++fm)
                ldsm4(af[fm], abase + fm * 16 * ROWB + kb);
            uint32_t bfr[8][2];
#pragma unroll
            for (int j = 0; j < 4; ++j) {
                uint32_t r[4];
                ldsm4(r, bbase + j * 16 * ROWB + kb);
                bfr[2 * j][0] = r[0]; bfr[2 * j][1] = r[1];
                bfr[2 * j + 1][0] = r[2]; bfr[2 * j + 1][1] = r[3];
            }
#pragma unroll
            for (int fm = 0; fm < 2; ++fm)
#pragma unroll
                for (int fn = 0; fn < 8; ++fn)
                    mma16816(acc[fm][fn], af[fm], bfr[fn]);
        }
    }

#pragma unroll
    for (int fm = 0; fm < 2; ++fm) {
        const int row0 = bm + wm * 32 + fm * 16 + (lane >> 2);
        const int b0 = row0 / NTOK,        n0 = row0 - b0 * NTOK;
        const int b1 = (row0 + 8) / NTOK,  n1 = (row0 + 8) - b1 * NTOK;
#pragma unroll
        for (int fn = 0; fn < 8; ++fn) {
            const int col = bn + wn * 64 + fn * 8 + (lane & 3) * 2;
            const float b0f = __ldg(&bias[col]);
            const float b1f = __ldg(&bias[col + 1]);
            float o0 = acc[fm][fn][0] + b0f, o1 = acc[fm][fn][1] + b1f;
            float o2 = acc[fm][fn][2] + b0f, o3 = acc[fm][fn][3] + b1f;
            if (mode == 0) {
                float* C = (float*)Cv;
                *reinterpret_cast<float2*>(&C[(size_t)row0 * ldc + col]) =
                    make_float2(o0, o1);
                *reinterpret_cast<float2*>(&C[(size_t)(row0 + 8) * ldc + col]) =
                    make_float2(o2, o3);
            } else if (col < 768) {
                if (col < 384) {        // q: fold softmax scale
                    o0 *= SCALE; o1 *= SCALE; o2 *= SCALE; o3 *= SCALE;
                }
                // permute within 32-elem head group: d -> slot*8 + g*2 (+sub)
                const int d   = col & 31;                 // even
                const int pos = ((d & 7) >> 1) * 8 + ((d >> 3) << 1);
                const int cb  = (col & ~31) + pos;
                *reinterpret_cast<uint32_t*>(&g_qkh[(size_t)row0 * 768 + cb]) =
                    pack2(__float2half_rn(o0), __float2half_rn(o1));
                *reinterpret_cast<uint32_t*>(&g_qkh[(size_t)(row0 + 8) * 768 + cb]) =
                    pack2(__float2half_rn(o2), __float2half_rn(o3));
            } else {
                const int cv = col - 768;
                // permute key within 64-key row: k -> slot*16 + g*2 + sub
                const int p0 = ((n0 & 7) >> 1) * 16 + ((n0 >> 3) << 1) + (n0 & 1);
                const int p1 = ((n1 & 7) >> 1) * 16 + ((n1 >> 3) << 1) + (n1 & 1);
                const size_t i0 = ((size_t)b0 * CDIM + cv) * 64 + p0;
                const size_t i1 = ((size_t)b1 * CDIM + cv) * 64 + p1;
                g_vt[i0]      = __float2half_rn(o0);
                g_vt[i0 + 64] = __float2half_rn(o1);
                g_vt[i1]      = __float2half_rn(o2);
                g_vt[i1 + 64] = __float2half_rn(o3);
            }
        }
    }
}

// -------------------- MMA attention: uint4 frag loads, K hoisted ------------
__global__ __launch_bounds__(256)
void attn_mma_kernel(const float* __restrict__ relb,
                     const float* __restrict__ mask)
{
    __shared__ float bias_s[NTOK * BSTR];

    const int w = blockIdx.x, h = blockIdx.y;
    const int tid = threadIdx.x, warp = tid >> 5, lane = tid & 31;
    const int kq = lane >> 2;
    const int kc = (lane & 3) * 2;
    const int g  = lane & 3;                 // perm block index

    {
        const float* rb = relb + (size_t)h * NTOK * NTOK;
        const float* mk = mask + (size_t)w * NTOK * NTOK;
        for (int i = tid; i < NTOK * NTOK; i += 256)
            bias_s[(i / NTOK) * BSTR + (i % NTOK)] = rb[i] + mk[i];
    }
    __syncthreads();

    for (int win = 0; win < 4; ++win) {
        const int j = warp * 4 + win;        // 0..31
        const int b = j * 64 + w;
        const __half* qsec = g_qkh + (size_t)b * NTOK * 768 + h * DHEAD;
        const __half* ksec = qsec + 384;
        const __half* vrow = g_vt + ((size_t)b * CDIM + h * DHEAD) * 64;

        // K frags: one uint4 per key row, loaded ONCE per window (hoisted)
        uint32_t kf[7][2][2];
#pragma unroll
        for (int nt = 0; nt < 7; ++nt) {
            const int key = nt * 8 + kq;
            uint4 u = make_uint4(0, 0, 0, 0);
            if (key < NTOK)
                u = *reinterpret_cast<const uint4*>(ksec + (size_t)key * 768 + g * 8);
            kf[nt][0][0] = u.x; kf[nt][0][1] = u.y;
            kf[nt][1][0] = u.z; kf[nt][1][1] = u.w;
        }
        // V frags: two uint4 per d-row, loaded once per window
        uint32_t vhf[4][4][2];
#pragma unroll
        for (int nt = 0; nt < 4; ++nt) {
            const __half* p = vrow + (size_t)(nt * 8 + kq) * 64 + g * 16;
            const uint4 u0 = *reinterpret_cast<const uint4*>(p);
            const uint4 u1 = *reinterpret_cast<const uint4*>(p + 8);
            vhf[nt][0][0] = u0.x; vhf[nt][0][1] = u0.y;
            vhf[nt][1][0] = u0.z; vhf[nt][1][1] = u0.w;
            vhf[nt][2][0] = u1.x; vhf[nt][2][1] = u1.y;
            vhf[nt][3][0] = u1.z; vhf[nt][3][1] = u1.w;
        }

        for (int mt = 0; mt < 4; ++mt) {
            const int row = mt * 16 + kq;
            const bool r0ok = (row < NTOK), r1ok = (row + 8 < NTOK);

            // Q frags: one uint4 per row
            uint32_t qf[2][4];
            {
                uint4 u0 = make_uint4(0, 0, 0, 0), u1 = make_uint4(0, 0, 0, 0);
                if (r0ok) u0 = *reinterpret_cast<const uint4*>(
                                   qsec + (size_t)row * 768 + g * 8);
                if (r1ok) u1 = *reinterpret_cast<const uint4*>(
                                   qsec + (size_t)(row + 8) * 768 + g * 8);
                qf[0][0] = u0.x; qf[0][2] = u0.y; qf[1][0] = u0.z; qf[1][2] = u0.w;
                qf[0][1] = u1.x; qf[0][3] = u1.y; qf[1][1] = u1.z; qf[1][3] = u1.w;
            }

            float sf[7][4];
#pragma unroll
            for (int nt = 0; nt < 7; ++nt) {
                sf[nt][0] = sf[nt][1] = sf[nt][2] = sf[nt][3] = 0.f;
                mma16816(sf[nt], qf[0], kf[nt][0]);
                mma16816(sf[nt], qf[1], kf[nt][1]);
            }

            const int n0 = (row < 48) ? row : 48;
            const int n1 = (row + 8 < 48) ? (row + 8) : 48;
            float sum0 = 0.f, sum1 = 0.f;
#pragma unroll
            for (int nt = 0; nt < 7; ++nt) {
                const int key = nt * 8 + kc;
                const float2 bq0 = *reinterpret_cast<const float2*>(&bias_s[n0 * BSTR + key]);
                const float2 bq1 = *reinterpret_cast<const float2*>(&bias_s[n1 * BSTR + key]);
                float e0 = __expf(sf[nt][0] + bq0.x);
                float e1 = __expf(sf[nt][1] + bq0.y);
                float e2 = __expf(sf[nt][2] + bq1.x);
                float e3 = __expf(sf[nt][3] + bq1.y);
                if (nt == 6) {
                    if (kc != 0) { e0 = 0.f; e2 = 0.f; }
                    e1 = 0.f; e3 = 0.f;
                }
                sf[nt][0] = e0; sf[nt][1] = e1; sf[nt][2] = e2; sf[nt][3] = e3;
                sum0 += e0 + e1; sum1 += e2 + e3;
            }
            sum0 += __shfl_xor_sync(0xffffffffu, sum0, 1);
            sum0 += __shfl_xor_sync(0xffffffffu, sum0, 2);
            sum1 += __shfl_xor_sync(0xffffffffu, sum1, 1);
            sum1 += __shfl_xor_sync(0xffffffffu, sum1, 2);
            const float inv0 = 1.f / sum0, inv1 = 1.f / sum1;

            float of[4][4];
#pragma unroll
            for (int nt = 0; nt < 4; ++nt)
                of[nt][0] = of[nt][1] = of[nt][2] = of[nt][3] = 0.f;

#pragma unroll
            for (int kt = 0; kt < 4; ++kt) {
                float e[8];
                e[0] = sf[2 * kt][0]; e[1] = sf[2 * kt][1];
                e[2] = sf[2 * kt][2]; e[3] = sf[2 * kt][3];
                if (2 * kt + 1 < 7) {
                    e[4] = sf[2 * kt + 1][0]; e[5] = sf[2 * kt + 1][1];
                    e[6] = sf[2 * kt + 1][2]; e[7] = sf[2 * kt + 1][3];
                } else {
                    e[4] = e[5] = e[6] = e[7] = 0.f;
                }
                __half hb[8], lb[8];
#pragma unroll
                for (int i = 0; i < 8; ++i) {
                    hb[i] = __float2half_rn(e[i]);
                    lb[i] = __float2half_rn(e[i] - __half2float(hb[i]));
                }
                uint32_t ph[4], pl[4];
                ph[0] = pack2(hb[0], hb[1]); ph[1] = pack2(hb[2], hb[3]);
                ph[2] = pack2(hb[4], hb[5]); ph[3] = pack2(hb[6], hb[7]);
                pl[0] = pack2(lb[0], lb[1]); pl[1] = pack2(lb[2], lb[3]);
                pl[2] = pack2(lb[4], lb[5]); pl[3] = pack2(lb[6], lb[7]);
#pragma unroll
                for (int nt = 0; nt < 4; ++nt) {
                    mma16816(of[nt], ph, vhf[nt][kt]);
                    mma16816(of[nt], pl, vhf[nt][kt]);
                }
            }

            const size_t r0 = ((size_t)b * NTOK + row) * CDIM + h * DHEAD;
            const size_t r1 = ((size_t)b * NTOK + row + 8) * CDIM + h * DHEAD;
#pragma unroll
            for (int nt = 0; nt < 4; ++nt) {
                const int d = nt * 8 + kc;
                if (r0ok) {
                    *reinterpret_cast<uint32_t*>(&g_attf[r0 + d]) =
                        pack2(__float2half_rn(of[nt][0] * inv0),
                              __float2half_rn(of[nt][1] * inv0));
                }
                if (r1ok) {
                    *reinterpret_cast<uint32_t*>(&g_attf[r1 + d]) =
                        pack2(__float2half_rn(of[nt][2] * inv1),
                              __float2half_rn(of[nt][3] * inv1));
                }
            }
        }
    }
}

// ---------------------------------------------------------------------------
extern "C" void kernel_launch(void* const* d_in, const int* in_sizes, int n_in,
                              void* d_out, int out_size)
{
    const float* x      = (const float*)d_in[0];
    const float* mask   = (const float*)d_in[1];
    const float* qkv_w  = (const float*)d_in[2];
    const float* qkv_b  = (const float*)d_in[3];
    const float* proj_w = (const float*)d_in[4];
    const float* proj_b = (const float*)d_in[5];
    const float* relb   = (const float*)d_in[6];
    float* out = (float*)d_out;

    void *p_xh, *p_attf, *p_wq, *p_wp;
    cudaGetSymbolAddress(&p_xh,   g_xh);
    cudaGetSymbolAddress(&p_attf, g_attf);
    cudaGetSymbolAddress(&p_wq,   g_wq);
    cudaGetSymbolAddress(&p_wp,   g_wp);

    cudaFuncSetAttribute(gemm_fp16_kernel,
                         cudaFuncAttributeMaxDynamicSharedMemorySize, SMEM_GEMM);

    // 0) fused preps
    prep_all_kernel<<<PX_BLKS + WQ_BLKS + WP_BLKS + PAD_BLKS, 256>>>(x, qkv_w, proj_w);

    // 1) fused QKV GEMM (R15 shape, permuted q/k/v outputs)
    {
        dim3 grid(QKVC / GBN, MTILES);    // 9 x 784
        gemm_fp16_kernel<<<grid, 256, SMEM_GEMM>>>(
            (const __half*)p_xh, KDIM, (const __half*)p_wq,
            qkv_b, nullptr, 0, 3);
    }
    // 2) MMA attention (uint4 frag loads, K hoisted per window)
    {
        dim3 grid(NWIN, HNUM);
        attn_mma_kernel<<<grid, 256>>>(relb, mask);
    }
    // 3) projection GEMM
    {
        dim3 grid(CDIM / GBN, MTILES);    // 3 x 784
        gemm_fp16_kernel<<<grid, 256, SMEM_GEMM>>>(
            (const __half*)p_attf, CDIM, (const __half*)p_wp,
            proj_b, out, CDIM, 0);
    }
}